// round 12
// baseline (speedup 1.0000x reference)
#include <cuda_runtime.h>
#include <cuda_bf16.h>

// out[flat] = x[flat] + pe[flat & 65535]   (x: 32M fp32, pe row-broadcast)
// pe[n,2k]   = sin(n / (2000*k/256 + 0.01))
// pe[n,2k+1] = cos(n / (2000*k/256 + 0.01))
//
// R8: contiguous-footprint streaming (R7 with fixed iteration stride).
// Block b owns flat float4 range [b*4096, (b+1)*4096) (64KB). Each
// super-iteration advances 1024 float4 (16KB); a thread's 4 batched loads
// are 256 float4 (4KB) apart, all inside the block's chunk. pe from the
// L2-hot 1MB table via (idx & 0xFFFF).

#define N_POS 1024
#define ROW_VEC 64                  // float4 per pe row
#define PE_VEC (N_POS * ROW_VEC)    // 65536 float4, mask 0xFFFF
#define TOTAL_VEC (128 * PE_VEC)    // 8388608 float4
#define BLK_VEC 4096                // float4 per block (64KB)
#define BATCH 4

__device__ float4 g_pe[PE_VEC];     // 1 MB table

__global__ void pe_init_kernel() {
    int t = blockIdx.x * blockDim.x + threadIdx.x;   // (n,k) pair, 0..131071
    int n = t >> 7;
    int k = t & 127;
    const float denom = (2000.0f / 256.0f) * (float)k + 0.01f;
    float s, c;
    sincosf((float)n / denom, &s, &c);
    reinterpret_cast<float2*>(g_pe)[t] = make_float2(s, c);
}

__global__ void __launch_bounds__(256) add_pe_stream(const float4* __restrict__ x,
                                                     float4* __restrict__ out) {
    const unsigned base = blockIdx.x * (unsigned)BLK_VEC + threadIdx.x;

#pragma unroll
    for (int it = 0; it < BLK_VEC / (BATCH * 256); ++it) {       // 4 iters
        const unsigned o = base + (unsigned)it * (BATCH * 256);  // +1024/iter
        float4 a0 = __ldcs(&x[o + 0u * 256u]);
        float4 a1 = __ldcs(&x[o + 1u * 256u]);
        float4 a2 = __ldcs(&x[o + 2u * 256u]);
        float4 a3 = __ldcs(&x[o + 3u * 256u]);
        const float4 p0 = __ldg(&g_pe[(o + 0u * 256u) & (PE_VEC - 1)]);
        const float4 p1 = __ldg(&g_pe[(o + 1u * 256u) & (PE_VEC - 1)]);
        const float4 p2 = __ldg(&g_pe[(o + 2u * 256u) & (PE_VEC - 1)]);
        const float4 p3 = __ldg(&g_pe[(o + 3u * 256u) & (PE_VEC - 1)]);
        a0.x += p0.x; a0.y += p0.y; a0.z += p0.z; a0.w += p0.w;
        a1.x += p1.x; a1.y += p1.y; a1.z += p1.z; a1.w += p1.w;
        a2.x += p2.x; a2.y += p2.y; a2.z += p2.z; a2.w += p2.w;
        a3.x += p3.x; a3.y += p3.y; a3.z += p3.z; a3.w += p3.w;
        __stcs(&out[o + 0u * 256u], a0);
        __stcs(&out[o + 1u * 256u], a1);
        __stcs(&out[o + 2u * 256u], a2);
        __stcs(&out[o + 3u * 256u], a3);
    }
}

extern "C" void kernel_launch(void* const* d_in, const int* in_sizes, int n_in,
                              void* d_out, int out_size) {
    const float4* x = (const float4*)d_in[0];
    float4* out = (float4*)d_out;

    pe_init_kernel<<<512, 256>>>();
    add_pe_stream<<<TOTAL_VEC / BLK_VEC, 256>>>(x, out);        // 2048 blocks
}